// round 1
// baseline (speedup 1.0000x reference)
#include <cuda_runtime.h>
#include <cuda_bf16.h>

#define NN 100000
#define EE 1600000
#define FIN 128
#define HH 64
#define OUTF 32
#define NB_SCAN 98   // ceil(100000/1024)

// ---------------- scratch (device globals; no allocation) ----------------
__device__ float g_h1[NN * HH];
__device__ float g_out1[NN * HH];
__device__ float g_h2[NN * HH];
__device__ float g_out2[NN * HH];
__device__ float g_asrc[NN];
__device__ float g_adst[NN];
__device__ int   g_deg[NN];
__device__ int   g_rowptr[NN + 1];
__device__ int   g_cursor[NN];
__device__ int   g_csr_src[EE];
__device__ int   g_bsum[128];

// ---------------- GEMM: [nrows x K] @ [K x 64] -> [nrows x 64] ----------------
// 256 threads, tile 64 rows x 64 cols, K chunked by 64.
template <int K, bool RELU>
__global__ void gemm_tile(const float* __restrict__ X, const float* __restrict__ W,
                          float* __restrict__ Y, int nrows) {
    __shared__ float xs[64][68];   // [k][row], padded
    __shared__ float ws[64][64];   // [k][col]
    int tid = threadIdx.x;
    int tn = (tid & 15) * 4;       // row offset within tile
    int tc = (tid >> 4) * 4;       // col offset within tile
    int row0 = blockIdx.x * 64;

    float acc[4][4];
#pragma unroll
    for (int i = 0; i < 4; i++)
#pragma unroll
        for (int j = 0; j < 4; j++) acc[i][j] = 0.f;

    for (int k0 = 0; k0 < K; k0 += 64) {
        // load X chunk transposed: xs[k][r]
        for (int idx = tid; idx < 64 * 64; idx += 256) {
            int r = idx >> 6, k = idx & 63;
            int row = row0 + r;
            float v = (row < nrows) ? X[row * K + k0 + k] : 0.f;
            if (RELU) v = fmaxf(v, 0.f);
            xs[k][r] = v;
        }
        // load W chunk
        for (int idx = tid; idx < 64 * 64; idx += 256) {
            int k = idx >> 6, c = idx & 63;
            ws[k][c] = W[(k0 + k) * 64 + c];
        }
        __syncthreads();
#pragma unroll 8
        for (int kk = 0; kk < 64; ++kk) {
            float4 a = *(const float4*)&xs[kk][tn];
            float4 b = *(const float4*)&ws[kk][tc];
            acc[0][0] += a.x * b.x; acc[0][1] += a.x * b.y; acc[0][2] += a.x * b.z; acc[0][3] += a.x * b.w;
            acc[1][0] += a.y * b.x; acc[1][1] += a.y * b.y; acc[1][2] += a.y * b.z; acc[1][3] += a.y * b.w;
            acc[2][0] += a.z * b.x; acc[2][1] += a.z * b.y; acc[2][2] += a.z * b.z; acc[2][3] += a.z * b.w;
            acc[3][0] += a.w * b.x; acc[3][1] += a.w * b.y; acc[3][2] += a.w * b.z; acc[3][3] += a.w * b.w;
        }
        __syncthreads();
    }
#pragma unroll
    for (int i = 0; i < 4; i++) {
        int row = row0 + tn + i;
        if (row < nrows) {
            float4 v = make_float4(acc[i][0], acc[i][1], acc[i][2], acc[i][3]);
            *(float4*)&Y[row * 64 + tc] = v;
        }
    }
}

// ---------------- per-node attention dot products ----------------
__global__ void attdot_k(const float* __restrict__ h, const float* __restrict__ as,
                         const float* __restrict__ ad) {
    int gw = (blockIdx.x * blockDim.x + threadIdx.x) >> 5;
    int lane = threadIdx.x & 31;
    if (gw >= NN) return;
    float h0 = h[gw * 64 + lane];
    float h1 = h[gw * 64 + 32 + lane];
    float ps = h0 * as[lane] + h1 * as[lane + 32];
    float pd = h0 * ad[lane] + h1 * ad[lane + 32];
#pragma unroll
    for (int off = 16; off; off >>= 1) {
        ps += __shfl_xor_sync(0xffffffffu, ps, off);
        pd += __shfl_xor_sync(0xffffffffu, pd, off);
    }
    if (lane == 0) { g_asrc[gw] = ps; g_adst[gw] = pd; }
}

// ---------------- CSR build ----------------
__global__ void zero_deg_k() {
    int i = blockIdx.x * blockDim.x + threadIdx.x;
    if (i < NN) g_deg[i] = 0;
}
__global__ void hist_k(const int* __restrict__ ei) {
    int i = blockIdx.x * blockDim.x + threadIdx.x;
    if (i < EE) atomicAdd(&g_deg[ei[EE + i]], 1);
}
__global__ void scan1_k() {
    __shared__ int s[1024];
    int tid = threadIdx.x;
    int i = blockIdx.x * 1024 + tid;
    int v = (i < NN) ? g_deg[i] : 0;
    s[tid] = v;
    __syncthreads();
#pragma unroll
    for (int off = 1; off < 1024; off <<= 1) {
        int t = (tid >= off) ? s[tid - off] : 0;
        __syncthreads();
        s[tid] += t;
        __syncthreads();
    }
    if (i < NN) g_rowptr[i] = s[tid] - v;   // exclusive within block
    if (tid == 1023) g_bsum[blockIdx.x] = s[1023];
}
__global__ void scan2_k() {
    __shared__ int s[128];
    int tid = threadIdx.x;
    int v = (tid < NB_SCAN) ? g_bsum[tid] : 0;
    s[tid] = v;
    __syncthreads();
#pragma unroll
    for (int off = 1; off < 128; off <<= 1) {
        int t = (tid >= off) ? s[tid - off] : 0;
        __syncthreads();
        s[tid] += t;
        __syncthreads();
    }
    g_bsum[tid] = s[tid] - v;   // exclusive
    if (tid == 127) g_rowptr[NN] = s[127];
}
__global__ void scan3_k() {
    int i = blockIdx.x * 1024 + threadIdx.x;
    if (i < NN) {
        int r = g_rowptr[i] + g_bsum[blockIdx.x];
        g_rowptr[i] = r;
        g_cursor[i] = r;
    }
}
__global__ void scatter_k(const int* __restrict__ ei) {
    int i = blockIdx.x * blockDim.x + threadIdx.x;
    if (i < EE) {
        int d = ei[EE + i];
        int p = atomicAdd(&g_cursor[d], 1);
        g_csr_src[p] = ei[i];
    }
}

// ---------------- fused segment softmax + aggregate (warp per dst node) --------
__global__ void agg_k(const float* __restrict__ h, const float* __restrict__ bias,
                      float* __restrict__ out) {
    int gw = (blockIdx.x * blockDim.x + threadIdx.x) >> 5;
    int lane = threadIdx.x & 31;
    if (gw >= NN) return;
    int start = g_rowptr[gw];
    int end = g_rowptr[gw + 1];
    float ad = g_adst[gw];

    // pass 1: max logit
    float m = -3.0e38f;
    for (int j = start + lane; j < end; j += 32) {
        int s = g_csr_src[j];
        float e = g_asrc[s] + ad;
        e = (e >= 0.f) ? e : 0.2f * e;
        m = fmaxf(m, e);
    }
#pragma unroll
    for (int off = 16; off; off >>= 1) m = fmaxf(m, __shfl_xor_sync(0xffffffffu, m, off));

    // pass 2: exp weights + weighted feature gather
    float ssum = 0.f, acc0 = 0.f, acc1 = 0.f;
    for (int j0 = start; j0 < end; j0 += 32) {
        int j = j0 + lane;
        int s = 0; float w = 0.f;
        if (j < end) {
            s = g_csr_src[j];
            float e = g_asrc[s] + ad;
            e = (e >= 0.f) ? e : 0.2f * e;
            w = __expf(e - m);
        }
        ssum += w;
        int cnt = min(32, end - j0);
        for (int c = 0; c < cnt; c++) {
            float wc = __shfl_sync(0xffffffffu, w, c);
            int sc = __shfl_sync(0xffffffffu, s, c);
            acc0 += wc * __ldg(&h[sc * 64 + lane]);
            acc1 += wc * __ldg(&h[sc * 64 + 32 + lane]);
        }
    }
#pragma unroll
    for (int off = 16; off; off >>= 1) ssum += __shfl_xor_sync(0xffffffffu, ssum, off);

    float inv = 1.0f / (ssum + 1e-16f);
    out[gw * 64 + lane]      = acc0 * inv + bias[lane];
    out[gw * 64 + 32 + lane] = acc1 * inv + bias[lane + 32];
}

// ---------------- final linear + log_softmax (warp per node) ----------------
__global__ void final_k(const float* __restrict__ h, const float* __restrict__ Wl,
                        const float* __restrict__ bl, float* __restrict__ out) {
    __shared__ float ws[64 * 32];
    __shared__ float bs[32];
    for (int i = threadIdx.x; i < 64 * 32; i += 256) ws[i] = Wl[i];
    if (threadIdx.x < 32) bs[threadIdx.x] = bl[threadIdx.x];
    __syncthreads();

    int gw = (blockIdx.x * blockDim.x + threadIdx.x) >> 5;
    int lane = threadIdx.x & 31;
    if (gw >= NN) return;
    float h0 = h[gw * 64 + lane];
    float h1 = h[gw * 64 + 32 + lane];
    float acc = bs[lane];
#pragma unroll
    for (int k = 0; k < 64; k++) {
        float xk = __shfl_sync(0xffffffffu, (k < 32) ? h0 : h1, k & 31);
        acc += xk * ws[k * 32 + lane];
    }
    // log softmax over the 32 lanes
    float mx = acc;
#pragma unroll
    for (int off = 16; off; off >>= 1) mx = fmaxf(mx, __shfl_xor_sync(0xffffffffu, mx, off));
    float ex = __expf(acc - mx);
    float sum = ex;
#pragma unroll
    for (int off = 16; off; off >>= 1) sum += __shfl_xor_sync(0xffffffffu, sum, off);
    out[gw * 32 + lane] = acc - mx - __logf(sum);
}

// ---------------- launch ----------------
static void build_csr(const int* ei) {
    zero_deg_k<<<(NN + 255) / 256, 256>>>();
    hist_k<<<EE / 256, 256>>>(ei);
    scan1_k<<<NB_SCAN, 1024>>>();
    scan2_k<<<1, 128>>>();
    scan3_k<<<NB_SCAN, 1024>>>();
    scatter_k<<<EE / 256, 256>>>(ei);
}

extern "C" void kernel_launch(void* const* d_in, const int* in_sizes, int n_in,
                              void* d_out, int out_size) {
    const float* x    = (const float*)d_in[0];
    const int*   ei1  = (const int*)d_in[1];
    const int*   ei2  = (const int*)d_in[2];
    const float* W1   = (const float*)d_in[3];
    const float* as1  = (const float*)d_in[4];
    const float* ad1  = (const float*)d_in[5];
    const float* b1   = (const float*)d_in[6];
    const float* W2   = (const float*)d_in[7];
    const float* as2  = (const float*)d_in[8];
    const float* ad2  = (const float*)d_in[9];
    const float* b2   = (const float*)d_in[10];
    const float* Wlin = (const float*)d_in[11];
    const float* blin = (const float*)d_in[12];
    float* out = (float*)d_out;

    float *h1, *o1, *h2, *o2;
    cudaGetSymbolAddress((void**)&h1, g_h1);
    cudaGetSymbolAddress((void**)&o1, g_out1);
    cudaGetSymbolAddress((void**)&h2, g_h2);
    cudaGetSymbolAddress((void**)&o2, g_out2);

    const int gemm_grid = (NN + 63) / 64;
    const int warp_grid = (NN + 7) / 8;   // 8 warps/block, warp per node

    // ---- layer 1 ----
    gemm_tile<FIN, false><<<gemm_grid, 256>>>(x, W1, h1, NN);
    attdot_k<<<warp_grid, 256>>>(h1, as1, ad1);
    build_csr(ei1);
    agg_k<<<warp_grid, 256>>>(h1, b1, o1);

    // ---- layer 2 (relu fused into GEMM load) ----
    gemm_tile<HH, true><<<gemm_grid, 256>>>(o1, W2, h2, NN);
    attdot_k<<<warp_grid, 256>>>(h2, as2, ad2);
    build_csr(ei2);
    agg_k<<<warp_grid, 256>>>(h2, b2, o2);

    // ---- final linear + log_softmax ----
    final_k<<<warp_grid, 256>>>(o2, Wlin, blin, out);
}

// round 2
// speedup vs baseline: 1.1961x; 1.1961x over previous
#include <cuda_runtime.h>
#include <cuda_bf16.h>

#define NN 100000
#define EE 1600000
#define FIN 128
#define HH 64
#define OUTF 32
#define NB_SCAN 98   // ceil(100000/1024)

// ---------------- scratch (device globals; no allocation) ----------------
__device__ float g_h[NN * HH];        // gemm output (reused by both layers)
__device__ float g_o[NN * HH];        // agg1 output / gemm2 input
__device__ float g_asrc[NN];
__device__ float g_adst[NN];
__device__ int   g_deg[2 * NN];
__device__ int   g_rowptr[2 * (NN + 1)];
__device__ int   g_cursor[2 * NN];
__device__ int   g_csr_src[2 * EE];
__device__ int   g_bsum[2 * 128];

// ---------------- GEMM + fused attention dots ----------------
// [nrows x K] @ [K x 64] -> [nrows x 64]; also a_src/a_dst per row.
template <int K, bool RELU>
__global__ void gemm_att(const float* __restrict__ X, const float* __restrict__ W,
                         float* __restrict__ Y,
                         const float* __restrict__ av_s, const float* __restrict__ av_d,
                         int nrows) {
    __shared__ float xs[64][68];      // [k][row], padded
    __shared__ float ws[64][64];      // [k][col]
    __shared__ float redp[16][64];    // per-colgroup partial src dots
    __shared__ float redd[16][64];    // per-colgroup partial dst dots
    int tid = threadIdx.x;
    int tn = (tid & 15) * 4;          // row offset within tile
    int g  = tid >> 4;                // col group 0..15
    int tc = g * 4;                   // col offset within tile
    int row0 = blockIdx.x * 64;

    float acc[4][4];
#pragma unroll
    for (int i = 0; i < 4; i++)
#pragma unroll
        for (int j = 0; j < 4; j++) acc[i][j] = 0.f;

    for (int k0 = 0; k0 < K; k0 += 64) {
        for (int idx = tid; idx < 64 * 64; idx += 256) {
            int r = idx >> 6, k = idx & 63;
            int row = row0 + r;
            float v = (row < nrows) ? X[row * K + k0 + k] : 0.f;
            if (RELU) v = fmaxf(v, 0.f);
            xs[k][r] = v;
        }
        for (int idx = tid; idx < 64 * 64; idx += 256) {
            int k = idx >> 6, c = idx & 63;
            ws[k][c] = W[(k0 + k) * 64 + c];
        }
        __syncthreads();
#pragma unroll 8
        for (int kk = 0; kk < 64; ++kk) {
            float4 a = *(const float4*)&xs[kk][tn];
            float4 b = *(const float4*)&ws[kk][tc];
            acc[0][0] += a.x * b.x; acc[0][1] += a.x * b.y; acc[0][2] += a.x * b.z; acc[0][3] += a.x * b.w;
            acc[1][0] += a.y * b.x; acc[1][1] += a.y * b.y; acc[1][2] += a.y * b.z; acc[1][3] += a.y * b.w;
            acc[2][0] += a.z * b.x; acc[2][1] += a.z * b.y; acc[2][2] += a.z * b.z; acc[2][3] += a.z * b.w;
            acc[3][0] += a.w * b.x; acc[3][1] += a.w * b.y; acc[3][2] += a.w * b.z; acc[3][3] += a.w * b.w;
        }
        __syncthreads();
    }

    // write Y + compute per-row partial attention dots
    float as0 = av_s[tc], as1 = av_s[tc + 1], as2 = av_s[tc + 2], as3 = av_s[tc + 3];
    float ad0 = av_d[tc], ad1 = av_d[tc + 1], ad2 = av_d[tc + 2], ad3 = av_d[tc + 3];
#pragma unroll
    for (int i = 0; i < 4; i++) {
        int row = row0 + tn + i;
        if (row < nrows) {
            float4 v = make_float4(acc[i][0], acc[i][1], acc[i][2], acc[i][3]);
            *(float4*)&Y[row * 64 + tc] = v;
        }
        redp[g][tn + i] = acc[i][0] * as0 + acc[i][1] * as1 + acc[i][2] * as2 + acc[i][3] * as3;
        redd[g][tn + i] = acc[i][0] * ad0 + acc[i][1] * ad1 + acc[i][2] * ad2 + acc[i][3] * ad3;
    }
    __syncthreads();
    if (tid < 64) {
        int row = row0 + tid;
        float ps = 0.f, pd = 0.f;
#pragma unroll
        for (int c = 0; c < 16; c++) { ps += redp[c][tid]; pd += redd[c][tid]; }
        if (row < nrows) { g_asrc[row] = ps; g_adst[row] = pd; }
    }
}

// ---------------- CSR build (both graphs at once) ----------------
__global__ void zero2_k() {
    int i = blockIdx.x * blockDim.x + threadIdx.x;
    if (i < 2 * NN) g_deg[i] = 0;
}
__global__ void hist2_k(const int* __restrict__ e1, const int* __restrict__ e2) {
    int i = blockIdx.x * blockDim.x + threadIdx.x;   // 0..2E
    int L = (i >= EE);
    const int* e = L ? e2 : e1;
    int idx = L ? (i - EE) : i;
    atomicAdd(&g_deg[L * NN + e[EE + idx]], 1);
}
__global__ void scan1_k() {
    __shared__ int s[1024];
    int L = blockIdx.y;
    int tid = threadIdx.x;
    int i = blockIdx.x * 1024 + tid;
    int v = (i < NN) ? g_deg[L * NN + i] : 0;
    s[tid] = v;
    __syncthreads();
#pragma unroll
    for (int off = 1; off < 1024; off <<= 1) {
        int t = (tid >= off) ? s[tid - off] : 0;
        __syncthreads();
        s[tid] += t;
        __syncthreads();
    }
    if (i < NN) g_rowptr[L * (NN + 1) + i] = s[tid] - v;
    if (tid == 1023) g_bsum[L * 128 + blockIdx.x] = s[1023];
}
__global__ void scan2_k() {
    __shared__ int s[128];
    int L = blockIdx.x;
    int tid = threadIdx.x;
    int v = (tid < NB_SCAN) ? g_bsum[L * 128 + tid] : 0;
    s[tid] = v;
    __syncthreads();
#pragma unroll
    for (int off = 1; off < 128; off <<= 1) {
        int t = (tid >= off) ? s[tid - off] : 0;
        __syncthreads();
        s[tid] += t;
        __syncthreads();
    }
    g_bsum[L * 128 + tid] = s[tid] - v;
    if (tid == 127) g_rowptr[L * (NN + 1) + NN] = s[127];
}
__global__ void scan3_k() {
    int L = blockIdx.y;
    int i = blockIdx.x * 1024 + threadIdx.x;
    if (i < NN) {
        int r = g_rowptr[L * (NN + 1) + i] + g_bsum[L * 128 + blockIdx.x];
        g_rowptr[L * (NN + 1) + i] = r;
        g_cursor[L * NN + i] = r;
    }
}
__global__ void scatter2_k(const int* __restrict__ e1, const int* __restrict__ e2) {
    int i = blockIdx.x * blockDim.x + threadIdx.x;
    int L = (i >= EE);
    const int* e = L ? e2 : e1;
    int idx = L ? (i - EE) : i;
    int d = e[EE + idx];
    int p = atomicAdd(&g_cursor[L * NN + d], 1);
    g_csr_src[L * EE + p] = e[idx];
}

// ---------------- fused segment softmax + aggregate ----------------
// warp per dst node; half-warp per edge, float4 feature gather.
// FINAL: also applies Wlin+blin and log_softmax, writing [N,32].
template <bool FINAL>
__global__ void agg_k(const float* __restrict__ h, const float* __restrict__ bias,
                      float* __restrict__ out,
                      const int* __restrict__ rowptr, const int* __restrict__ csr,
                      const float* __restrict__ Wl, const float* __restrict__ bl) {
    __shared__ float wsh[64 * 32];
    if (FINAL) {
        for (int i = threadIdx.x; i < 64 * 32; i += 256) wsh[i] = Wl[i];
        __syncthreads();
    }
    int gw = (blockIdx.x * blockDim.x + threadIdx.x) >> 5;
    int lane = threadIdx.x & 31;
    if (gw >= NN) return;
    int half = lane >> 4;
    int q = (lane & 15) * 4;          // feature column group
    int start = rowptr[gw];
    int end = rowptr[gw + 1];
    float ad = g_adst[gw];

    float4 acc = make_float4(0.f, 0.f, 0.f, 0.f);
    float ssum = 0.f;
    for (int j0 = start; j0 < end; j0 += 32) {
        int j = j0 + lane;
        int s = 0; float w = 0.f;
        if (j < end) {
            s = csr[j];
            float e = __ldg(&g_asrc[s]) + ad;
            e = (e >= 0.f) ? e : 0.2f * e;
            w = __expf(e);
        }
        ssum += w;
        int cnt = min(32, end - j0);
        for (int p2 = 0; p2 < cnt; p2 += 2) {
            int ei = p2 + half;
            float wc = __shfl_sync(0xffffffffu, w, ei & 31);
            int   sc = __shfl_sync(0xffffffffu, s, ei & 31);
            if (ei < cnt) {
                float4 hv = *(const float4*)(h + sc * 64 + q);
                acc.x += wc * hv.x; acc.y += wc * hv.y;
                acc.z += wc * hv.z; acc.w += wc * hv.w;
            }
        }
    }
    // cross-half + full reductions
    acc.x += __shfl_xor_sync(0xffffffffu, acc.x, 16);
    acc.y += __shfl_xor_sync(0xffffffffu, acc.y, 16);
    acc.z += __shfl_xor_sync(0xffffffffu, acc.z, 16);
    acc.w += __shfl_xor_sync(0xffffffffu, acc.w, 16);
#pragma unroll
    for (int off = 16; off; off >>= 1) ssum += __shfl_xor_sync(0xffffffffu, ssum, off);
    float inv = 1.0f / (ssum + 1e-16f);

    float4 b4 = *(const float4*)(bias + q);
    float4 o;
    o.x = acc.x * inv + b4.x; o.y = acc.y * inv + b4.y;
    o.z = acc.z * inv + b4.z; o.w = acc.w * inv + b4.w;

    if (!FINAL) {
        if (half == 0) *(float4*)(out + gw * 64 + q) = o;
    } else {
        // final linear [64x32] + log_softmax across 32 lanes
        float oarr[4] = {o.x, o.y, o.z, o.w};
        float accl = __ldg(&bl[lane]);
#pragma unroll
        for (int k = 0; k < 64; k++) {
            float xk = __shfl_sync(0xffffffffu, oarr[k & 3], k >> 2);
            accl += xk * wsh[k * 32 + lane];
        }
        float mx = accl;
#pragma unroll
        for (int off = 16; off; off >>= 1) mx = fmaxf(mx, __shfl_xor_sync(0xffffffffu, mx, off));
        float ex = __expf(accl - mx);
        float sum = ex;
#pragma unroll
        for (int off = 16; off; off >>= 1) sum += __shfl_xor_sync(0xffffffffu, sum, off);
        out[gw * 32 + lane] = accl - mx - __logf(sum);
    }
}

// ---------------- launch ----------------
extern "C" void kernel_launch(void* const* d_in, const int* in_sizes, int n_in,
                              void* d_out, int out_size) {
    const float* x    = (const float*)d_in[0];
    const int*   ei1  = (const int*)d_in[1];
    const int*   ei2  = (const int*)d_in[2];
    const float* W1   = (const float*)d_in[3];
    const float* as1  = (const float*)d_in[4];
    const float* ad1  = (const float*)d_in[5];
    const float* b1   = (const float*)d_in[6];
    const float* W2   = (const float*)d_in[7];
    const float* as2  = (const float*)d_in[8];
    const float* ad2  = (const float*)d_in[9];
    const float* b2   = (const float*)d_in[10];
    const float* Wlin = (const float*)d_in[11];
    const float* blin = (const float*)d_in[12];
    float* out = (float*)d_out;

    float *h, *o;
    int *rowptr, *csr;
    cudaGetSymbolAddress((void**)&h, g_h);
    cudaGetSymbolAddress((void**)&o, g_o);
    cudaGetSymbolAddress((void**)&rowptr, g_rowptr);
    cudaGetSymbolAddress((void**)&csr, g_csr_src);

    const int gemm_grid = (NN + 63) / 64;
    const int warp_grid = (NN + 7) / 8;    // warp per node, 8 warps/block

    // ---- both CSR builds up front ----
    zero2_k<<<(2 * NN + 255) / 256, 256>>>();
    hist2_k<<<2 * EE / 256, 256>>>(ei1, ei2);
    scan1_k<<<dim3(NB_SCAN, 2), 1024>>>();
    scan2_k<<<2, 128>>>();
    scan3_k<<<dim3(NB_SCAN, 2), 1024>>>();
    scatter2_k<<<2 * EE / 256, 256>>>(ei1, ei2);

    // ---- layer 1 ----
    gemm_att<FIN, false><<<gemm_grid, 256>>>(x, W1, h, as1, ad1, NN);
    agg_k<false><<<warp_grid, 256>>>(h, b1, o, rowptr, csr, nullptr, nullptr);

    // ---- layer 2 (relu fused into GEMM load) + final fused into agg ----
    gemm_att<HH, true><<<gemm_grid, 256>>>(o, W2, h, as2, ad2, NN);
    agg_k<true><<<warp_grid, 256>>>(h, b2, out, rowptr + (NN + 1), csr + EE,
                                    Wlin, blin);
}

// round 3
// speedup vs baseline: 1.7469x; 1.4605x over previous
#include <cuda_runtime.h>
#include <cuda_bf16.h>

#define NN 100000
#define EE 1600000
#define FIN 128
#define HH 64
#define OUTF 32
#define NB_SCAN 98   // ceil(100000/1024)

// ---------------- scratch (device globals; no allocation) ----------------
__device__ float g_h[NN * HH];        // gemm output (reused by both layers)
__device__ float g_o[NN * HH];        // agg1 output / gemm2 input
__device__ float g_asrc[NN];
__device__ float g_adst[NN];
__device__ int   g_deg[2 * NN];
__device__ int   g_rowptr[2 * (NN + 1)];
__device__ int   g_cursor[2 * NN];
__device__ int   g_csr_src[2 * EE];
__device__ int   g_bsum[2 * 128];

// ---------------- GEMM + fused attention dots ----------------
template <int K, bool RELU>
__global__ void gemm_att(const float* __restrict__ X, const float* __restrict__ W,
                         float* __restrict__ Y,
                         const float* __restrict__ av_s, const float* __restrict__ av_d,
                         int nrows) {
    __shared__ float xs[64][68];
    __shared__ float ws[64][64];
    __shared__ float redp[16][64];
    __shared__ float redd[16][64];
    int tid = threadIdx.x;
    int tn = (tid & 15) * 4;
    int g  = tid >> 4;
    int tc = g * 4;
    int row0 = blockIdx.x * 64;

    float acc[4][4];
#pragma unroll
    for (int i = 0; i < 4; i++)
#pragma unroll
        for (int j = 0; j < 4; j++) acc[i][j] = 0.f;

    for (int k0 = 0; k0 < K; k0 += 64) {
        for (int idx = tid; idx < 64 * 64; idx += 256) {
            int r = idx >> 6, k = idx & 63;
            int row = row0 + r;
            float v = (row < nrows) ? X[row * K + k0 + k] : 0.f;
            if (RELU) v = fmaxf(v, 0.f);
            xs[k][r] = v;
        }
        for (int idx = tid; idx < 64 * 64; idx += 256) {
            int k = idx >> 6, c = idx & 63;
            ws[k][c] = W[(k0 + k) * 64 + c];
        }
        __syncthreads();
#pragma unroll 8
        for (int kk = 0; kk < 64; ++kk) {
            float4 a = *(const float4*)&xs[kk][tn];
            float4 b = *(const float4*)&ws[kk][tc];
            acc[0][0] += a.x * b.x; acc[0][1] += a.x * b.y; acc[0][2] += a.x * b.z; acc[0][3] += a.x * b.w;
            acc[1][0] += a.y * b.x; acc[1][1] += a.y * b.y; acc[1][2] += a.y * b.z; acc[1][3] += a.y * b.w;
            acc[2][0] += a.z * b.x; acc[2][1] += a.z * b.y; acc[2][2] += a.z * b.z; acc[2][3] += a.z * b.w;
            acc[3][0] += a.w * b.x; acc[3][1] += a.w * b.y; acc[3][2] += a.w * b.z; acc[3][3] += a.w * b.w;
        }
        __syncthreads();
    }

    float as0 = av_s[tc], as1 = av_s[tc + 1], as2 = av_s[tc + 2], as3 = av_s[tc + 3];
    float ad0 = av_d[tc], ad1 = av_d[tc + 1], ad2 = av_d[tc + 2], ad3 = av_d[tc + 3];
#pragma unroll
    for (int i = 0; i < 4; i++) {
        int row = row0 + tn + i;
        if (row < nrows) {
            float4 v = make_float4(acc[i][0], acc[i][1], acc[i][2], acc[i][3]);
            *(float4*)&Y[row * 64 + tc] = v;
        }
        redp[g][tn + i] = acc[i][0] * as0 + acc[i][1] * as1 + acc[i][2] * as2 + acc[i][3] * as3;
        redd[g][tn + i] = acc[i][0] * ad0 + acc[i][1] * ad1 + acc[i][2] * ad2 + acc[i][3] * ad3;
    }
    __syncthreads();
    if (tid < 64) {
        int row = row0 + tid;
        float ps = 0.f, pd = 0.f;
#pragma unroll
        for (int c = 0; c < 16; c++) { ps += redp[c][tid]; pd += redd[c][tid]; }
        if (row < nrows) { g_asrc[row] = ps; g_adst[row] = pd; }
    }
}

// ---------------- CSR build (both graphs at once) ----------------
__global__ void zero2_k() {
    int i = blockIdx.x * blockDim.x + threadIdx.x;
    if (i < 2 * NN) g_deg[i] = 0;
}
__global__ void hist2_k(const int* __restrict__ e1, const int* __restrict__ e2) {
    int i = blockIdx.x * blockDim.x + threadIdx.x;
    int L = (i >= EE);
    const int* e = L ? e2 : e1;
    int idx = L ? (i - EE) : i;
    atomicAdd(&g_deg[L * NN + e[EE + idx]], 1);
}
__global__ void scan1_k() {
    __shared__ int s[1024];
    int L = blockIdx.y;
    int tid = threadIdx.x;
    int i = blockIdx.x * 1024 + tid;
    int v = (i < NN) ? g_deg[L * NN + i] : 0;
    s[tid] = v;
    __syncthreads();
#pragma unroll
    for (int off = 1; off < 1024; off <<= 1) {
        int t = (tid >= off) ? s[tid - off] : 0;
        __syncthreads();
        s[tid] += t;
        __syncthreads();
    }
    if (i < NN) g_rowptr[L * (NN + 1) + i] = s[tid] - v;
    if (tid == 1023) g_bsum[L * 128 + blockIdx.x] = s[1023];
}
// merged scan2+scan3: each block derives its own bsum-prefix
__global__ void scan23_k() {
    __shared__ int bpart[128];
    __shared__ int base_s;
    int L = blockIdx.y;
    int b = blockIdx.x;
    int tid = threadIdx.x;
    if (tid < 128) bpart[tid] = (tid < b) ? g_bsum[L * 128 + tid] : 0;
    __syncthreads();
    if (tid < 64) bpart[tid] += bpart[tid + 64];
    __syncthreads();
    if (tid < 32) {
        int v = bpart[tid] + bpart[tid + 32];
#pragma unroll
        for (int off = 16; off; off >>= 1) v += __shfl_xor_sync(0xffffffffu, v, off);
        if (tid == 0) base_s = v;
    }
    __syncthreads();
    int i = b * 1024 + tid;
    if (i < NN) {
        int r = g_rowptr[L * (NN + 1) + i] + base_s;
        g_rowptr[L * (NN + 1) + i] = r;
        g_cursor[L * NN + i] = r;
    }
    if (b == 0 && tid == 0) g_rowptr[L * (NN + 1) + NN] = EE;  // total is constant
}
__global__ void scatter2_k(const int* __restrict__ e1, const int* __restrict__ e2) {
    int i = blockIdx.x * blockDim.x + threadIdx.x;
    int L = (i >= EE);
    const int* e = L ? e2 : e1;
    int idx = L ? (i - EE) : i;
    int d = e[EE + idx];
    int p = atomicAdd(&g_cursor[L * NN + d], 1);
    g_csr_src[L * EE + p] = e[idx];
}

// ---------------- fused segment softmax + aggregate ----------------
// warp per dst node; half-warp per edge, float4 gather, 4 edges in flight.
template <bool FINAL>
__global__ void agg_k(const float* __restrict__ h, const float* __restrict__ bias,
                      float* __restrict__ out,
                      const int* __restrict__ rowptr, const int* __restrict__ csr,
                      const float* __restrict__ Wl, const float* __restrict__ bl) {
    __shared__ float wsh[64 * 32];
    if (FINAL) {
        for (int i = threadIdx.x; i < 64 * 32; i += 256) wsh[i] = Wl[i];
        __syncthreads();
    }
    int gw = (blockIdx.x * blockDim.x + threadIdx.x) >> 5;
    int lane = threadIdx.x & 31;
    if (gw >= NN) return;
    int half = lane >> 4;
    int q = (lane & 15) * 4;
    int start = rowptr[gw];
    int end = rowptr[gw + 1];
    float ad = g_adst[gw];

    float4 acc = make_float4(0.f, 0.f, 0.f, 0.f);
    float ssum = 0.f;
    for (int j0 = start; j0 < end; j0 += 32) {
        int j = j0 + lane;
        int s = 0; float w = 0.f;
        if (j < end) {
            s = csr[j];
            float e = __ldg(&g_asrc[s]) + ad;
            e = (e >= 0.f) ? e : 0.2f * e;
            w = __expf(e);
        }
        ssum += w;
        int cnt = min(32, end - j0);
        int p2 = 0;
        // main: 4 edges per iteration (2 independent LDG.128 per lane)
        for (; p2 + 4 <= cnt; p2 += 4) {
            int e0 = p2 + half, e1 = p2 + 2 + half;
            float w0 = __shfl_sync(0xffffffffu, w, e0);
            int   s0 = __shfl_sync(0xffffffffu, s, e0);
            float w1 = __shfl_sync(0xffffffffu, w, e1);
            int   s1 = __shfl_sync(0xffffffffu, s, e1);
            float4 h0 = *(const float4*)(h + s0 * 64 + q);
            float4 h1 = *(const float4*)(h + s1 * 64 + q);
            acc.x += w0 * h0.x + w1 * h1.x;
            acc.y += w0 * h0.y + w1 * h1.y;
            acc.z += w0 * h0.z + w1 * h1.z;
            acc.w += w0 * h0.w + w1 * h1.w;
        }
        // tail: 2 edges per iteration, predicated
        for (; p2 < cnt; p2 += 2) {
            int ei = p2 + half;
            int eic = (ei < cnt) ? ei : (cnt - 1);
            float wc = __shfl_sync(0xffffffffu, w, eic);
            int   sc = __shfl_sync(0xffffffffu, s, eic);
            if (ei < cnt) {
                float4 hv = *(const float4*)(h + sc * 64 + q);
                acc.x += wc * hv.x; acc.y += wc * hv.y;
                acc.z += wc * hv.z; acc.w += wc * hv.w;
            }
        }
    }
    acc.x += __shfl_xor_sync(0xffffffffu, acc.x, 16);
    acc.y += __shfl_xor_sync(0xffffffffu, acc.y, 16);
    acc.z += __shfl_xor_sync(0xffffffffu, acc.z, 16);
    acc.w += __shfl_xor_sync(0xffffffffu, acc.w, 16);
#pragma unroll
    for (int off = 16; off; off >>= 1) ssum += __shfl_xor_sync(0xffffffffu, ssum, off);
    float inv = 1.0f / (ssum + 1e-16f);

    float4 b4 = *(const float4*)(bias + q);
    float4 o;
    o.x = acc.x * inv + b4.x; o.y = acc.y * inv + b4.y;
    o.z = acc.z * inv + b4.z; o.w = acc.w * inv + b4.w;

    if (!FINAL) {
        if (half == 0) *(float4*)(out + gw * 64 + q) = o;
    } else {
        float oarr[4] = {o.x, o.y, o.z, o.w};
        float accl = __ldg(&bl[lane]);
#pragma unroll
        for (int k = 0; k < 64; k++) {
            float xk = __shfl_sync(0xffffffffu, oarr[k & 3], k >> 2);
            accl += xk * wsh[k * 32 + lane];
        }
        float mx = accl;
#pragma unroll
        for (int off = 16; off; off >>= 1) mx = fmaxf(mx, __shfl_xor_sync(0xffffffffu, mx, off));
        float ex = __expf(accl - mx);
        float sum = ex;
#pragma unroll
        for (int off = 16; off; off >>= 1) sum += __shfl_xor_sync(0xffffffffu, sum, off);
        out[gw * 32 + lane] = accl - mx - __logf(sum);
    }
}

// ---------------- launch ----------------
extern "C" void kernel_launch(void* const* d_in, const int* in_sizes, int n_in,
                              void* d_out, int out_size) {
    const float* x    = (const float*)d_in[0];
    const int*   ei1  = (const int*)d_in[1];
    const int*   ei2  = (const int*)d_in[2];
    const float* W1   = (const float*)d_in[3];
    const float* as1  = (const float*)d_in[4];
    const float* ad1  = (const float*)d_in[5];
    const float* b1   = (const float*)d_in[6];
    const float* W2   = (const float*)d_in[7];
    const float* as2  = (const float*)d_in[8];
    const float* ad2  = (const float*)d_in[9];
    const float* b2   = (const float*)d_in[10];
    const float* Wlin = (const float*)d_in[11];
    const float* blin = (const float*)d_in[12];
    float* out = (float*)d_out;

    float *h, *o;
    int *rowptr, *csr;
    cudaGetSymbolAddress((void**)&h, g_h);
    cudaGetSymbolAddress((void**)&o, g_o);
    cudaGetSymbolAddress((void**)&rowptr, g_rowptr);
    cudaGetSymbolAddress((void**)&csr, g_csr_src);

    // side stream + fork/join events (created once; no device memory involved)
    static cudaStream_t s_side = nullptr;
    static cudaEvent_t ev_fork = nullptr, ev_join = nullptr;
    if (s_side == nullptr) {
        cudaStreamCreateWithFlags(&s_side, cudaStreamNonBlocking);
        cudaEventCreateWithFlags(&ev_fork, cudaEventDisableTiming);
        cudaEventCreateWithFlags(&ev_join, cudaEventDisableTiming);
    }

    const int gemm_grid = (NN + 63) / 64;
    const int warp_grid = (NN + 7) / 8;

    // ---- fork: CSR build for both graphs on side stream ----
    cudaEventRecord(ev_fork, 0);
    cudaStreamWaitEvent(s_side, ev_fork, 0);
    zero2_k<<<(2 * NN + 255) / 256, 256, 0, s_side>>>();
    hist2_k<<<2 * EE / 256, 256, 0, s_side>>>(ei1, ei2);
    scan1_k<<<dim3(NB_SCAN, 2), 1024, 0, s_side>>>();
    scan23_k<<<dim3(NB_SCAN, 2), 1024, 0, s_side>>>();
    scatter2_k<<<2 * EE / 256, 256, 0, s_side>>>(ei1, ei2);
    cudaEventRecord(ev_join, s_side);

    // ---- main stream: gemm1 overlaps CSR build ----
    gemm_att<FIN, false><<<gemm_grid, 256>>>(x, W1, h, as1, ad1, NN);
    cudaStreamWaitEvent(0, ev_join, 0);   // join before aggregation

    agg_k<false><<<warp_grid, 256>>>(h, b1, o, rowptr, csr, nullptr, nullptr);
    gemm_att<HH, true><<<gemm_grid, 256>>>(o, W2, h, as2, ad2, NN);
    agg_k<true><<<warp_grid, 256>>>(h, b2, out, rowptr + (NN + 1), csr + EE,
                                    Wlin, blin);
}

// round 4
// speedup vs baseline: 1.7833x; 1.0208x over previous
#include <cuda_runtime.h>
#include <cuda_bf16.h>

#define NN 100000
#define EE 1600000
#define FIN 128
#define HH 64
#define OUTF 32
#define NB_SCAN 98   // ceil(100000/1024)

// ---------------- scratch (device globals; no allocation) ----------------
__device__ float g_h[NN * HH];
__device__ float g_o[NN * HH];
__device__ float g_asrc[NN];
__device__ float g_adst[NN];
__device__ int   g_deg[2 * NN];
__device__ int   g_rowptr[2 * (NN + 1)];
__device__ int   g_cursor[2 * NN];
__device__ int   g_csr_src[2 * EE];
__device__ int   g_bsum[2 * 128];

// ---------------- GEMM + fused attention dots ----------------
template <int K, bool RELU>
__global__ void gemm_att(const float* __restrict__ X, const float* __restrict__ W,
                         float* __restrict__ Y,
                         const float* __restrict__ av_s, const float* __restrict__ av_d,
                         int nrows) {
    __shared__ float xs[64][68];
    __shared__ float ws[64][64];
    __shared__ float redp[16][64];
    __shared__ float redd[16][64];
    int tid = threadIdx.x;
    int tn = (tid & 15) * 4;
    int g  = tid >> 4;
    int tc = g * 4;
    int row0 = blockIdx.x * 64;

    float acc[4][4];
#pragma unroll
    for (int i = 0; i < 4; i++)
#pragma unroll
        for (int j = 0; j < 4; j++) acc[i][j] = 0.f;

    for (int k0 = 0; k0 < K; k0 += 64) {
        for (int idx = tid; idx < 64 * 64; idx += 256) {
            int r = idx >> 6, k = idx & 63;
            int row = row0 + r;
            float v = (row < nrows) ? X[row * K + k0 + k] : 0.f;
            if (RELU) v = fmaxf(v, 0.f);
            xs[k][r] = v;
        }
        for (int idx = tid; idx < 64 * 64; idx += 256) {
            int k = idx >> 6, c = idx & 63;
            ws[k][c] = W[(k0 + k) * 64 + c];
        }
        __syncthreads();
#pragma unroll 8
        for (int kk = 0; kk < 64; ++kk) {
            float4 a = *(const float4*)&xs[kk][tn];
            float4 b = *(const float4*)&ws[kk][tc];
            acc[0][0] += a.x * b.x; acc[0][1] += a.x * b.y; acc[0][2] += a.x * b.z; acc[0][3] += a.x * b.w;
            acc[1][0] += a.y * b.x; acc[1][1] += a.y * b.y; acc[1][2] += a.y * b.z; acc[1][3] += a.y * b.w;
            acc[2][0] += a.z * b.x; acc[2][1] += a.z * b.y; acc[2][2] += a.z * b.z; acc[2][3] += a.z * b.w;
            acc[3][0] += a.w * b.x; acc[3][1] += a.w * b.y; acc[3][2] += a.w * b.z; acc[3][3] += a.w * b.w;
        }
        __syncthreads();
    }

    float as0 = av_s[tc], as1 = av_s[tc + 1], as2 = av_s[tc + 2], as3 = av_s[tc + 3];
    float ad0 = av_d[tc], ad1 = av_d[tc + 1], ad2 = av_d[tc + 2], ad3 = av_d[tc + 3];
#pragma unroll
    for (int i = 0; i < 4; i++) {
        int row = row0 + tn + i;
        if (row < nrows) {
            float4 v = make_float4(acc[i][0], acc[i][1], acc[i][2], acc[i][3]);
            *(float4*)&Y[row * 64 + tc] = v;
        }
        redp[g][tn + i] = acc[i][0] * as0 + acc[i][1] * as1 + acc[i][2] * as2 + acc[i][3] * as3;
        redd[g][tn + i] = acc[i][0] * ad0 + acc[i][1] * ad1 + acc[i][2] * ad2 + acc[i][3] * ad3;
    }
    __syncthreads();
    if (tid < 64) {
        int row = row0 + tid;
        float ps = 0.f, pd = 0.f;
#pragma unroll
        for (int c = 0; c < 16; c++) { ps += redp[c][tid]; pd += redd[c][tid]; }
        if (row < nrows) { g_asrc[row] = ps; g_adst[row] = pd; }
    }
}

// ---------------- CSR build (per-graph chains) ----------------
__global__ void zero2_k() {
    int i = blockIdx.x * blockDim.x + threadIdx.x;
    if (i < 2 * NN) g_deg[i] = 0;
}
__global__ void hist_k(const int* __restrict__ e, int L) {
    int i = blockIdx.x * blockDim.x + threadIdx.x;
    if (i < EE) atomicAdd(&g_deg[L * NN + e[EE + i]], 1);
}
__global__ void scan1_k(int L) {
    __shared__ int s[1024];
    int tid = threadIdx.x;
    int i = blockIdx.x * 1024 + tid;
    int v = (i < NN) ? g_deg[L * NN + i] : 0;
    s[tid] = v;
    __syncthreads();
#pragma unroll
    for (int off = 1; off < 1024; off <<= 1) {
        int t = (tid >= off) ? s[tid - off] : 0;
        __syncthreads();
        s[tid] += t;
        __syncthreads();
    }
    if (i < NN) g_rowptr[L * (NN + 1) + i] = s[tid] - v;
    if (tid == 1023) g_bsum[L * 128 + blockIdx.x] = s[1023];
}
__global__ void scan23_k(int L) {
    __shared__ int bpart[128];
    __shared__ int base_s;
    int b = blockIdx.x;
    int tid = threadIdx.x;
    if (tid < 128) bpart[tid] = (tid < b) ? g_bsum[L * 128 + tid] : 0;
    __syncthreads();
    if (tid < 64) bpart[tid] += bpart[tid + 64];
    __syncthreads();
    if (tid < 32) {
        int v = bpart[tid] + bpart[tid + 32];
#pragma unroll
        for (int off = 16; off; off >>= 1) v += __shfl_xor_sync(0xffffffffu, v, off);
        if (tid == 0) base_s = v;
    }
    __syncthreads();
    int i = b * 1024 + tid;
    if (i < NN) {
        int r = g_rowptr[L * (NN + 1) + i] + base_s;
        g_rowptr[L * (NN + 1) + i] = r;
        g_cursor[L * NN + i] = r;
    }
    if (b == 0 && tid == 0) g_rowptr[L * (NN + 1) + NN] = EE;
}
__global__ void scatter_k(const int* __restrict__ e, int L) {
    int i = blockIdx.x * blockDim.x + threadIdx.x;
    if (i < EE) {
        int d = e[EE + i];
        int p = atomicAdd(&g_cursor[L * NN + d], 1);
        g_csr_src[L * EE + p] = e[i];
    }
}

// ---------------- fused segment softmax + aggregate ----------------
// warp per dst node; half-warp per edge, float4 gather, up to 8 edges in flight.
template <bool FINAL>
__global__ void agg_k(const float* __restrict__ h, const float* __restrict__ bias,
                      float* __restrict__ out,
                      const int* __restrict__ rowptr, const int* __restrict__ csr,
                      const float* __restrict__ Wl, const float* __restrict__ bl) {
    __shared__ float wsh[64 * 32];
    if (FINAL) {
        for (int i = threadIdx.x; i < 64 * 32; i += 256) wsh[i] = Wl[i];
        __syncthreads();
    }
    int gw = (blockIdx.x * blockDim.x + threadIdx.x) >> 5;
    int lane = threadIdx.x & 31;
    if (gw >= NN) return;
    int half = lane >> 4;
    int q = (lane & 15) * 4;
    int start = rowptr[gw];
    int end = rowptr[gw + 1];
    float ad = g_adst[gw];

    float4 acc = make_float4(0.f, 0.f, 0.f, 0.f);
    float ssum = 0.f;
    for (int j0 = start; j0 < end; j0 += 32) {
        int j = j0 + lane;
        int s = 0; float w = 0.f;
        if (j < end) {
            s = csr[j];
            float e = __ldg(&g_asrc[s]) + ad;
            e = (e >= 0.f) ? e : 0.2f * e;
            w = __expf(e);
        }
        ssum += w;
        int cnt = min(32, end - j0);
        int p2 = 0;
        // main: 8 edges per iteration (4 independent LDG.128 per lane)
        for (; p2 + 8 <= cnt; p2 += 8) {
            int e0 = p2 + half, e1 = p2 + 2 + half, e2 = p2 + 4 + half, e3 = p2 + 6 + half;
            float w0 = __shfl_sync(0xffffffffu, w, e0);
            int   s0 = __shfl_sync(0xffffffffu, s, e0);
            float w1 = __shfl_sync(0xffffffffu, w, e1);
            int   s1 = __shfl_sync(0xffffffffu, s, e1);
            float w2 = __shfl_sync(0xffffffffu, w, e2);
            int   s2 = __shfl_sync(0xffffffffu, s, e2);
            float w3 = __shfl_sync(0xffffffffu, w, e3);
            int   s3 = __shfl_sync(0xffffffffu, s, e3);
            float4 h0 = *(const float4*)(h + s0 * 64 + q);
            float4 h1 = *(const float4*)(h + s1 * 64 + q);
            float4 h2 = *(const float4*)(h + s2 * 64 + q);
            float4 h3 = *(const float4*)(h + s3 * 64 + q);
            acc.x += w0 * h0.x + w1 * h1.x + w2 * h2.x + w3 * h3.x;
            acc.y += w0 * h0.y + w1 * h1.y + w2 * h2.y + w3 * h3.y;
            acc.z += w0 * h0.z + w1 * h1.z + w2 * h2.z + w3 * h3.z;
            acc.w += w0 * h0.w + w1 * h1.w + w2 * h2.w + w3 * h3.w;
        }
        // tail: 2 edges per iteration, predicated
        for (; p2 < cnt; p2 += 2) {
            int ei = p2 + half;
            int eic = (ei < cnt) ? ei : (cnt - 1);
            float wc = __shfl_sync(0xffffffffu, w, eic);
            int   sc = __shfl_sync(0xffffffffu, s, eic);
            if (ei < cnt) {
                float4 hv = *(const float4*)(h + sc * 64 + q);
                acc.x += wc * hv.x; acc.y += wc * hv.y;
                acc.z += wc * hv.z; acc.w += wc * hv.w;
            }
        }
    }
    acc.x += __shfl_xor_sync(0xffffffffu, acc.x, 16);
    acc.y += __shfl_xor_sync(0xffffffffu, acc.y, 16);
    acc.z += __shfl_xor_sync(0xffffffffu, acc.z, 16);
    acc.w += __shfl_xor_sync(0xffffffffu, acc.w, 16);
#pragma unroll
    for (int off = 16; off; off >>= 1) ssum += __shfl_xor_sync(0xffffffffu, ssum, off);
    float inv = 1.0f / (ssum + 1e-16f);

    float4 b4 = *(const float4*)(bias + q);
    float4 o;
    o.x = acc.x * inv + b4.x; o.y = acc.y * inv + b4.y;
    o.z = acc.z * inv + b4.z; o.w = acc.w * inv + b4.w;

    if (!FINAL) {
        if (half == 0) *(float4*)(out + gw * 64 + q) = o;
    } else {
        float oarr[4] = {o.x, o.y, o.z, o.w};
        float accl = __ldg(&bl[lane]);
#pragma unroll
        for (int k = 0; k < 64; k++) {
            float xk = __shfl_sync(0xffffffffu, oarr[k & 3], k >> 2);
            accl += xk * wsh[k * 32 + lane];
        }
        float mx = accl;
#pragma unroll
        for (int off = 16; off; off >>= 1) mx = fmaxf(mx, __shfl_xor_sync(0xffffffffu, mx, off));
        float ex = __expf(accl - mx);
        float sum = ex;
#pragma unroll
        for (int off = 16; off; off >>= 1) sum += __shfl_xor_sync(0xffffffffu, sum, off);
        out[gw * 32 + lane] = accl - mx - __logf(sum);
    }
}

// ---------------- launch ----------------
extern "C" void kernel_launch(void* const* d_in, const int* in_sizes, int n_in,
                              void* d_out, int out_size) {
    const float* x    = (const float*)d_in[0];
    const int*   ei1  = (const int*)d_in[1];
    const int*   ei2  = (const int*)d_in[2];
    const float* W1   = (const float*)d_in[3];
    const float* as1  = (const float*)d_in[4];
    const float* ad1  = (const float*)d_in[5];
    const float* b1   = (const float*)d_in[6];
    const float* W2   = (const float*)d_in[7];
    const float* as2  = (const float*)d_in[8];
    const float* ad2  = (const float*)d_in[9];
    const float* b2   = (const float*)d_in[10];
    const float* Wlin = (const float*)d_in[11];
    const float* blin = (const float*)d_in[12];
    float* out = (float*)d_out;

    float *h, *o;
    int *rowptr, *csr;
    cudaGetSymbolAddress((void**)&h, g_h);
    cudaGetSymbolAddress((void**)&o, g_o);
    cudaGetSymbolAddress((void**)&rowptr, g_rowptr);
    cudaGetSymbolAddress((void**)&csr, g_csr_src);

    static cudaStream_t s_side = nullptr;
    static cudaEvent_t ev_fork = nullptr, ev_csr1 = nullptr, ev_csr2 = nullptr;
    if (s_side == nullptr) {
        cudaStreamCreateWithFlags(&s_side, cudaStreamNonBlocking);
        cudaEventCreateWithFlags(&ev_fork, cudaEventDisableTiming);
        cudaEventCreateWithFlags(&ev_csr1, cudaEventDisableTiming);
        cudaEventCreateWithFlags(&ev_csr2, cudaEventDisableTiming);
    }

    const int gemm_grid = (NN + 63) / 64;
    const int warp_grid = (NN + 7) / 8;
    const int egrid = EE / 256;

    // ---- fork: per-graph CSR chains on side stream ----
    cudaEventRecord(ev_fork, 0);
    cudaStreamWaitEvent(s_side, ev_fork, 0);
    zero2_k<<<(2 * NN + 255) / 256, 256, 0, s_side>>>();
    // graph 1 chain
    hist_k<<<egrid, 256, 0, s_side>>>(ei1, 0);
    scan1_k<<<NB_SCAN, 1024, 0, s_side>>>(0);
    scan23_k<<<NB_SCAN, 1024, 0, s_side>>>(0);
    scatter_k<<<egrid, 256, 0, s_side>>>(ei1, 0);
    cudaEventRecord(ev_csr1, s_side);
    // graph 2 chain (overlaps agg1 / gemm2 on main stream)
    hist_k<<<egrid, 256, 0, s_side>>>(ei2, 1);
    scan1_k<<<NB_SCAN, 1024, 0, s_side>>>(1);
    scan23_k<<<NB_SCAN, 1024, 0, s_side>>>(1);
    scatter_k<<<egrid, 256, 0, s_side>>>(ei2, 1);
    cudaEventRecord(ev_csr2, s_side);

    // ---- main stream ----
    gemm_att<FIN, false><<<gemm_grid, 256>>>(x, W1, h, as1, ad1, NN);
    cudaStreamWaitEvent(0, ev_csr1, 0);
    agg_k<false><<<warp_grid, 256>>>(h, b1, o, rowptr, csr, nullptr, nullptr);
    gemm_att<HH, true><<<gemm_grid, 256>>>(o, W2, h, as2, ad2, NN);
    cudaStreamWaitEvent(0, ev_csr2, 0);
    agg_k<true><<<warp_grid, 256>>>(h, b2, out, rowptr + (NN + 1), csr + EE,
                                    Wlin, blin);
}